// round 17
// baseline (speedup 1.0000x reference)
#include <cuda_runtime.h>
#include <cuda_bf16.h>
#include <math.h>

// Problem constants (match reference setup_inputs)
#define NSRC   200000
#define NF     128
#define NH     1500
#define NC     64
#define R0     50000
#define R1     10000
#define NHPAD  1536
#define MTILES 391
#define MROWS  (MTILES * 128)   // 50048
#define NT     24               // N-slabs of 64 covering 1500 (padded to 1536)
#define E0C    1600000
#define E1C    500000
#define TILES0 49               // ceil(R0/1024)
#define TILES1 10               // ceil(R1/1024)
#define NTILES (TILES0 + TILES1)

// ---------------- scratch (__device__ globals; no allocation allowed) --------
__device__ float d_g[R0 * NC];                // 12.8 MB
__device__ float d_yroot[R1 * NC];
__device__ int   d_emax[4];
__device__ int   d_cnt0[R0];
__device__ int   d_off0[R0 + 1];
__device__ int   d_cur0[R0];
__device__ int   d_csr0[E0C];
__device__ int   d_cnt1[R1];
__device__ int   d_off1[R1 + 1];
__device__ int   d_cur1[R1];
__device__ int   d_csr1[E1C];
__device__ int   d_tileagg[NTILES];
__device__ int   d_tilebase[NTILES];
__device__ __nv_bfloat16 d_xb[(size_t)NSRC * NF];     // 51.2 MB  x in bf16
__device__ __nv_bfloat16 d_Ab[(size_t)MROWS * 256];   // 25.6 MB  [x | xmean] bf16
__device__ __nv_bfloat16 d_W1b[NHPAD * 256];          // [n][k] = W1{r,n}[k][n]
__device__ __nv_bfloat16 d_W2nb[NC * NHPAD];          // [c][n] = W2n[n][c]
__device__ __nv_bfloat16 d_W2rb[NC * NHPAD];          // [c][n] = W2r[n][c]

__device__ __forceinline__ unsigned pack_bf16(float lo, float hi) {
    unsigned r;
    asm("cvt.rn.bf16x2.f32 %0, %1, %2;" : "=r"(r) : "f"(hi), "f"(lo));
    return r;
}

// ---------------- zero per-call-reset state (graph replays) -----------------
__global__ void zero_kernel() {
    int i = blockIdx.x * blockDim.x + threadIdx.x;
    if (i < R0) d_cnt0[i] = 0;
    if (i < R1) d_cnt1[i] = 0;
    if (i < 4)  d_emax[i] = 0;
}

// both edge pairs in one launch
__global__ void edgemax_kernel(const int* __restrict__ a0, const int* __restrict__ b0,
                               const int* __restrict__ a1, const int* __restrict__ b1) {
    __shared__ int s0, s1, s2, s3;
    if (threadIdx.x == 0) { s0 = 0; s1 = 0; s2 = 0; s3 = 0; }
    __syncthreads();
    int stride = gridDim.x * blockDim.x;
    int i0 = blockIdx.x * blockDim.x + threadIdx.x;
    int va = 0, vb = 0, vc = 0, vd = 0;
    for (int i = i0; i < E0C; i += stride) { va = max(va, a0[i]); vb = max(vb, b0[i]); }
    for (int i = i0; i < E1C; i += stride) { vc = max(vc, a1[i]); vd = max(vd, b1[i]); }
    atomicMax(&s0, va); atomicMax(&s1, vb); atomicMax(&s2, vc); atomicMax(&s3, vd);
    __syncthreads();
    if (threadIdx.x == 0) {
        atomicMax(&d_emax[0], s0); atomicMax(&d_emax[1], s1);
        atomicMax(&d_emax[2], s2); atomicMax(&d_emax[3], s3);
    }
}

// ---------------- CSR build: both layers per launch -------------------------
__global__ void hist_kernel(const int* __restrict__ eA0, const int* __restrict__ eB0,
                            const int* __restrict__ eA1, const int* __restrict__ eB1) {
    int i = blockIdx.x * blockDim.x + threadIdx.x;
    if (i < E0C) {
        bool a_is_src = d_emax[0] >= d_emax[1];
        int t = a_is_src ? eB0[i] : eA0[i];
        if ((unsigned)t < R0) atomicAdd(&d_cnt0[t], 1);
    }
    if (i < E1C) {
        bool a_is_src = d_emax[2] >= d_emax[3];
        int t = a_is_src ? eB1[i] : eA1[i];
        if ((unsigned)t < R1) atomicAdd(&d_cnt1[t], 1);
    }
}

// ------- 3-phase parallel scan ----------------------------------------------
__global__ void scan_local_kernel() {
    int b = blockIdx.x;
    int which = (b < TILES0) ? 0 : 1;
    int tile  = which ? (b - TILES0) : b;
    const int* cnt = which ? d_cnt1 : d_cnt0;
    int* off = which ? d_off1 : d_off0;
    int n    = which ? R1 : R0;
    int tid  = threadIdx.x;
    int lane = tid & 31, wid = tid >> 5;
    int idx  = tile * 1024 + tid;
    int v = (idx < n) ? cnt[idx] : 0;
    int incl = v;
#pragma unroll
    for (int o = 1; o < 32; o <<= 1) {
        int t = __shfl_up_sync(0xffffffffu, incl, o);
        if (lane >= o) incl += t;
    }
    __shared__ int wsum[32];
    if (lane == 31) wsum[wid] = incl;
    __syncthreads();
    if (wid == 0) {
        int w = wsum[lane];
        int wi = w;
#pragma unroll
        for (int o = 1; o < 32; o <<= 1) {
            int t = __shfl_up_sync(0xffffffffu, wi, o);
            if (lane >= o) wi += t;
        }
        wsum[lane] = wi - w;               // exclusive warp base
        if (lane == 31) d_tileagg[b] = wi; // tile total
    }
    __syncthreads();
    if (idx < n) off[idx] = wsum[wid] + incl - v;
}

__global__ void scan_spine_kernel() {
    if (threadIdx.x == 0) {
        int run = 0;
        for (int t = 0; t < TILES0; t++) { d_tilebase[t] = run; run += d_tileagg[t]; }
        d_off0[R0] = run;
    } else if (threadIdx.x == 1) {
        int run = 0;
        for (int t = 0; t < TILES1; t++) {
            d_tilebase[TILES0 + t] = run;
            run += d_tileagg[TILES0 + t];
        }
        d_off1[R1] = run;
    }
}

__global__ void scan_add_kernel() {
    int b = blockIdx.x;
    int which = (b < TILES0) ? 0 : 1;
    int tile  = which ? (b - TILES0) : b;
    int* off = which ? d_off1 : d_off0;
    int* cur = which ? d_cur1 : d_cur0;
    int n    = which ? R1 : R0;
    int idx = tile * 1024 + threadIdx.x;
    if (idx < n) {
        int o = off[idx] + d_tilebase[b];
        off[idx] = o;
        cur[idx] = o;
    }
}

__global__ void scatter_kernel(const int* __restrict__ eA0, const int* __restrict__ eB0,
                               const int* __restrict__ eA1, const int* __restrict__ eB1) {
    int i = blockIdx.x * blockDim.x + threadIdx.x;
    if (i < E0C) {
        bool a_is_src = d_emax[0] >= d_emax[1];
        int s = a_is_src ? eA0[i] : eB0[i];
        int t = a_is_src ? eB0[i] : eA0[i];
        if ((unsigned)t < R0 && (unsigned)s < NSRC) {
            int p = atomicAdd(&d_cur0[t], 1);
            d_csr0[p] = s;
        }
    }
    if (i < E1C) {
        bool a_is_src = d_emax[2] >= d_emax[3];
        int s = a_is_src ? eA1[i] : eB1[i];
        int t = a_is_src ? eB1[i] : eA1[i];
        if ((unsigned)t < R1 && (unsigned)s < R0) {
            int p = atomicAdd(&d_cur1[t], 1);
            d_csr1[p] = s;
        }
    }
}

// ---------------- x -> bf16 -------------------------------------------------
__global__ void convX_kernel(const float* __restrict__ x) {
    size_t i = (size_t)blockIdx.x * blockDim.x + threadIdx.x;   // one per 4 elems
    if (i >= (size_t)NSRC * NF / 4) return;
    float4 v = reinterpret_cast<const float4*>(x)[i];
    reinterpret_cast<uint2*>(d_xb)[i] =
        make_uint2(pack_bf16(v.x, v.y), pack_bf16(v.z, v.w));
}

// ---------------- gather + mean (LDG.128, 2 edges/warp in flight) -----------
__global__ void gather_conv_kernel() {
    int w    = (blockIdx.x * blockDim.x + threadIdx.x) >> 5;
    int lane = threadIdx.x & 31;
    if (w >= R0) return;
    int half = lane >> 4;       // 0 or 1
    int li   = lane & 15;       // 16B chunk index within row
    int beg = d_off0[w], end = d_off0[w + 1];
    float acc[8];
#pragma unroll
    for (int c = 0; c < 8; c++) acc[c] = 0.f;
    int e = beg + half;
    for (; e + 2 < end; e += 4) {
        int s0 = d_csr0[e], s1 = d_csr0[e + 2];
        uint4 u0 = *reinterpret_cast<const uint4*>(d_xb + (size_t)s0 * NF + li * 8);
        uint4 u1 = *reinterpret_cast<const uint4*>(d_xb + (size_t)s1 * NF + li * 8);
        const unsigned* p0 = &u0.x;
        const unsigned* p1 = &u1.x;
#pragma unroll
        for (int q = 0; q < 4; q++) {
            float2 f0 = __bfloat1622float2(*reinterpret_cast<const __nv_bfloat162*>(&p0[q]));
            float2 f1 = __bfloat1622float2(*reinterpret_cast<const __nv_bfloat162*>(&p1[q]));
            acc[q * 2 + 0] += f0.x + f1.x;
            acc[q * 2 + 1] += f0.y + f1.y;
        }
    }
    for (; e < end; e += 2) {
        int s0 = d_csr0[e];
        uint4 u0 = *reinterpret_cast<const uint4*>(d_xb + (size_t)s0 * NF + li * 8);
        const unsigned* p0 = &u0.x;
#pragma unroll
        for (int q = 0; q < 4; q++) {
            float2 f0 = __bfloat1622float2(*reinterpret_cast<const __nv_bfloat162*>(&p0[q]));
            acc[q * 2 + 0] += f0.x;
            acc[q * 2 + 1] += f0.y;
        }
    }
#pragma unroll
    for (int c = 0; c < 8; c++) acc[c] += __shfl_xor_sync(0xffffffffu, acc[c], 16);
    float inv = 1.f / fmaxf((float)(end - beg), 1.f);
    __nv_bfloat16* row = d_Ab + (size_t)w * 256;
    if (half == 0) {
        unsigned r0 = pack_bf16(acc[0] * inv, acc[1] * inv);
        unsigned r1 = pack_bf16(acc[2] * inv, acc[3] * inv);
        unsigned r2 = pack_bf16(acc[4] * inv, acc[5] * inv);
        unsigned r3 = pack_bf16(acc[6] * inv, acc[7] * inv);
        *reinterpret_cast<uint4*>(row + 128 + li * 8) = make_uint4(r0, r1, r2, r3);
        *reinterpret_cast<uint4*>(row + li * 8) =
            *reinterpret_cast<const uint4*>(d_xb + (size_t)w * NF + li * 8);
    }
}

// ---------------- bf16 weight preparation (merged) --------------------------
__global__ void convW_kernel(const float* __restrict__ W1r, const float* __restrict__ W1n,
                             const float* __restrict__ W2n, const float* __restrict__ W2r) {
    int i = blockIdx.x * blockDim.x + threadIdx.x;
    if (i < NHPAD * 256) {
        int n = i >> 8, k = i & 255;
        float v = 0.f;
        if (n < NH) v = (k < 128) ? W1r[(size_t)k * NH + n] : W1n[(size_t)(k - 128) * NH + n];
        d_W1b[i] = __float2bfloat16(v);
    }
    if (i < NC * NHPAD) {
        int c = i / NHPAD, n = i % NHPAD;
        float vn = 0.f, vr = 0.f;
        if (n < NH) { vn = W2n[(size_t)n * NC + c]; vr = W2r[(size_t)n * NC + c]; }
        d_W2nb[i] = __float2bfloat16(vn);
        d_W2rb[i] = __float2bfloat16(vr);
    }
}

// ---------------- HMMA helpers ----------------------------------------------
__device__ __forceinline__ void mma16816(float* c, unsigned a0, unsigned a1,
                                         unsigned a2, unsigned a3,
                                         unsigned b0, unsigned b1) {
    asm volatile(
        "mma.sync.aligned.m16n8k16.row.col.f32.bf16.bf16.f32 "
        "{%0,%1,%2,%3}, {%4,%5,%6,%7}, {%8,%9}, {%0,%1,%2,%3};"
        : "+f"(c[0]), "+f"(c[1]), "+f"(c[2]), "+f"(c[3])
        : "r"(a0), "r"(a1), "r"(a2), "r"(a3), "r"(b0), "r"(b1));
}
__device__ __forceinline__ void ldsm_x4(unsigned& r0, unsigned& r1,
                                        unsigned& r2, unsigned& r3, unsigned addr) {
    asm volatile("ldmatrix.sync.aligned.m8n8.x4.shared.b16 {%0,%1,%2,%3}, [%4];"
                 : "=r"(r0), "=r"(r1), "=r"(r2), "=r"(r3) : "r"(addr));
}

// ---------------- fused GEMM chain on HMMA tensor cores ---------------------
#define APITCH 264
#define BPITCH 264
#define WPITCH 72
#define SM_AS  0
#define SM_BS  (128 * APITCH)
#define SM_WS  (SM_BS + 64 * BPITCH)
#define SM_TOT ((SM_WS + 64 * WPITCH) * 2)     // bytes = 110592

__global__ __launch_bounds__(256, 2) void mma_fused_kernel(const float* __restrict__ b1) {
    extern __shared__ __nv_bfloat16 sm[];
    __nv_bfloat16* As = sm + SM_AS;
    __nv_bfloat16* Bs = sm + SM_BS;
    __nv_bfloat16* Ws = sm + SM_WS;
    int tid  = threadIdx.x;
    int warp = tid >> 5;
    int lane = tid & 31;
    int g    = lane >> 2;
    int tig  = lane & 3;
    int m0   = blockIdx.x * 128;
    int mrow = warp * 16;

    for (int idx = tid; idx < 128 * 32; idx += 256) {
        int row = idx >> 5, c8 = idx & 31;
        uint4 v = reinterpret_cast<const uint4*>(d_Ab + (size_t)(m0 + row) * 256)[c8];
        *reinterpret_cast<uint4*>(&As[row * APITCH + c8 * 8]) = v;
    }

    unsigned saA = (unsigned)__cvta_generic_to_shared(As);
    unsigned saB = (unsigned)__cvta_generic_to_shared(Bs);
    unsigned saW = (unsigned)__cvta_generic_to_shared(Ws);
    unsigned aBase = saA + ((mrow + (lane & 15)) * APITCH + (lane >> 4) * 8) * 2;
    unsigned bBase[4], wBase[4];
#pragma unroll
    for (int jp = 0; jp < 4; jp++) {
        int n   = jp * 16 + ((lane >> 4) & 1) * 8 + (lane & 7);
        int col = ((lane >> 3) & 1) * 8;
        bBase[jp] = saB + (n * BPITCH + col) * 2;
        wBase[jp] = saW + (n * WPITCH + col) * 2;
    }

    float accG[8][4], accY[8][4];
#pragma unroll
    for (int j = 0; j < 8; j++)
#pragma unroll
        for (int q = 0; q < 4; q++) { accG[j][q] = 0.f; accY[j][q] = 0.f; }

    const bool doY = (m0 < R1);

    for (int it = 0; it < NT; it++) {
        int n0 = it * 64;
        __syncthreads();
        for (int idx = tid; idx < 64 * 32; idx += 256) {
            int row = idx >> 5, c8 = idx & 31;
            uint4 v = reinterpret_cast<const uint4*>(d_W1b + (size_t)(n0 + row) * 256)[c8];
            *reinterpret_cast<uint4*>(&Bs[row * BPITCH + c8 * 8]) = v;
        }
        for (int idx = tid; idx < 64 * 8; idx += 256) {
            int row = idx >> 3, c8 = idx & 7;
            uint4 v = *reinterpret_cast<const uint4*>(d_W2nb + (size_t)row * NHPAD + n0 + c8 * 8);
            *reinterpret_cast<uint4*>(&Ws[row * WPITCH + c8 * 8]) = v;
        }
        __syncthreads();

        float accH[8][4];
#pragma unroll
        for (int j = 0; j < 8; j++)
#pragma unroll
            for (int q = 0; q < 4; q++) accH[j][q] = 0.f;

#pragma unroll 4
        for (int kk = 0; kk < 16; kk++) {
            unsigned a0, a1, a2, a3;
            ldsm_x4(a0, a1, a2, a3, aBase + kk * 32);
#pragma unroll
            for (int jp = 0; jp < 4; jp++) {
                unsigned r0, r1, r2, r3;
                ldsm_x4(r0, r1, r2, r3, bBase[jp] + kk * 32);
                mma16816(accH[jp * 2 + 0], a0, a1, a2, a3, r0, r1);
                mma16816(accH[jp * 2 + 1], a0, a1, a2, a3, r2, r3);
            }
        }

        unsigned hfrag[4][4];
#pragma unroll
        for (int j = 0; j < 8; j++) {
            int c0 = n0 + j * 8 + tig * 2;
            float bb0 = (c0     < NH) ? __ldg(b1 + c0)     : 0.f;
            float bb1 = (c0 + 1 < NH) ? __ldg(b1 + c0 + 1) : 0.f;
            float h0 = (c0     < NH) ? fmaxf(accH[j][0] + bb0, 0.f) : 0.f;
            float h1 = (c0 + 1 < NH) ? fmaxf(accH[j][1] + bb1, 0.f) : 0.f;
            float h2 = (c0     < NH) ? fmaxf(accH[j][2] + bb0, 0.f) : 0.f;
            float h3 = (c0 + 1 < NH) ? fmaxf(accH[j][3] + bb1, 0.f) : 0.f;
            hfrag[j >> 1][(j & 1) * 2 + 0] = pack_bf16(h0, h1);
            hfrag[j >> 1][(j & 1) * 2 + 1] = pack_bf16(h2, h3);
        }

#pragma unroll
        for (int kk = 0; kk < 4; kk++) {
            unsigned a0 = hfrag[kk][0], a1 = hfrag[kk][1];
            unsigned a2 = hfrag[kk][2], a3 = hfrag[kk][3];
#pragma unroll
            for (int jp = 0; jp < 4; jp++) {
                unsigned r0, r1, r2, r3;
                ldsm_x4(r0, r1, r2, r3, wBase[jp] + kk * 32);
                mma16816(accG[jp * 2 + 0], a0, a1, a2, a3, r0, r1);
                mma16816(accG[jp * 2 + 1], a0, a1, a2, a3, r2, r3);
            }
        }
        if (doY) {
#pragma unroll
            for (int kk = 0; kk < 4; kk++) {
                int kb = n0 + kk * 16;
                unsigned a0 = hfrag[kk][0], a1 = hfrag[kk][1];
                unsigned a2 = hfrag[kk][2], a3 = hfrag[kk][3];
#pragma unroll
                for (int j = 0; j < 8; j++) {
                    const __nv_bfloat16* bp = d_W2rb + (size_t)(j * 8 + g) * NHPAD + kb;
                    unsigned b0 = *reinterpret_cast<const unsigned*>(bp + tig * 2);
                    unsigned b1f = *reinterpret_cast<const unsigned*>(bp + 8 + tig * 2);
                    mma16816(accY[j], a0, a1, a2, a3, b0, b1f);
                }
            }
        }
    }

    {
        int gmA = m0 + mrow + g;
        int gmB = gmA + 8;
#pragma unroll
        for (int j = 0; j < 8; j++) {
            int c = j * 8 + tig * 2;
            if (gmA < R0)
                *reinterpret_cast<float2*>(d_g + (size_t)gmA * NC + c) =
                    make_float2(accG[j][0], accG[j][1]);
            if (gmB < R0)
                *reinterpret_cast<float2*>(d_g + (size_t)gmB * NC + c) =
                    make_float2(accG[j][2], accG[j][3]);
        }
        if (doY) {
#pragma unroll
            for (int j = 0; j < 8; j++) {
                int c = j * 8 + tig * 2;
                if (gmA < R1)
                    *reinterpret_cast<float2*>(d_yroot + (size_t)gmA * NC + c) =
                        make_float2(accY[j][0], accY[j][1]);
                if (gmB < R1)
                    *reinterpret_cast<float2*>(d_yroot + (size_t)gmB * NC + c) =
                        make_float2(accY[j][2], accY[j][3]);
            }
        }
    }
}

// ------- fused: gather-mean(g) + yroot + b2 + log_softmax (CSR, no atomics) -
__global__ void final_kernel(const float* __restrict__ b2, float* __restrict__ out) {
    int gid  = blockIdx.x * blockDim.x + threadIdx.x;
    int w    = gid >> 5;
    int lane = gid & 31;
    if (w >= R1) return;
    int beg = d_off1[w], end = d_off1[w + 1];
    float ax = 0.f, ay = 0.f, bx = 0.f, by = 0.f;
    int e = beg;
    for (; e + 1 < end; e += 2) {
        int s0 = d_csr1[e], s1 = d_csr1[e + 1];
        float2 v0 = *reinterpret_cast<const float2*>(d_g + (size_t)s0 * NC + lane * 2);
        float2 v1 = *reinterpret_cast<const float2*>(d_g + (size_t)s1 * NC + lane * 2);
        ax += v0.x; ay += v0.y; bx += v1.x; by += v1.y;
    }
    if (e < end) {
        int s0 = d_csr1[e];
        float2 v0 = *reinterpret_cast<const float2*>(d_g + (size_t)s0 * NC + lane * 2);
        ax += v0.x; ay += v0.y;
    }
    float inv = 1.f / fmaxf((float)(end - beg), 1.f);
    float vx = (ax + bx) * inv + d_yroot[w * NC + lane * 2 + 0] + b2[lane * 2 + 0];
    float vy = (ay + by) * inv + d_yroot[w * NC + lane * 2 + 1] + b2[lane * 2 + 1];
    float m = fmaxf(vx, vy);
#pragma unroll
    for (int o = 16; o; o >>= 1) m = fmaxf(m, __shfl_xor_sync(0xffffffffu, m, o));
    float s = expf(vx - m) + expf(vy - m);
#pragma unroll
    for (int o = 16; o; o >>= 1) s += __shfl_xor_sync(0xffffffffu, s, o);
    float lse = logf(s);
    out[w * NC + lane * 2 + 0] = vx - m - lse;
    out[w * NC + lane * 2 + 1] = vy - m - lse;
}

// ---------------- launch (multi-stream capture fork) ------------------------
extern "C" void kernel_launch(void* const* d_in, const int* in_sizes, int n_in,
                              void* d_out, int out_size) {
    const float *x = 0, *W1r = 0, *W1n = 0, *b1 = 0, *W2r = 0, *W2n = 0, *b2 = 0;
    const int *eA0 = 0, *eB0 = 0, *eA1 = 0, *eB1 = 0;
    for (int i = 0; i < n_in; i++) {
        int sz = in_sizes[i];
        const void* p = d_in[i];
        if      (sz == NSRC * NF) { x = (const float*)p; }
        else if (sz == NF * NH)   { if (!W1r) W1r = (const float*)p; else W1n = (const float*)p; }
        else if (sz == NH)        { b1 = (const float*)p; }
        else if (sz == NH * NC)   { if (!W2r) W2r = (const float*)p; else W2n = (const float*)p; }
        else if (sz == NC)        { b2 = (const float*)p; }
        else if (sz == E0C)       { if (!eA0) eA0 = (const int*)p; else eB0 = (const int*)p; }
        else if (sz == E1C)       { if (!eA1) eA1 = (const int*)p; else eB1 = (const int*)p; }
    }
    float* out = (float*)d_out;
    (void)out_size;

    // one-time setup on the first (uncaptured correctness) call
    static cudaStream_t s1 = 0, s2 = 0;
    static cudaEvent_t evFork = 0, evX = 0, evW = 0;
    static int init_done = 0;
    if (!init_done) {
        cudaFuncSetAttribute(mma_fused_kernel,
                             cudaFuncAttributeMaxDynamicSharedMemorySize, SM_TOT);
        cudaStreamCreateWithFlags(&s1, cudaStreamNonBlocking);
        cudaStreamCreateWithFlags(&s2, cudaStreamNonBlocking);
        cudaEventCreateWithFlags(&evFork, cudaEventDisableTiming);
        cudaEventCreateWithFlags(&evX, cudaEventDisableTiming);
        cudaEventCreateWithFlags(&evW, cudaEventDisableTiming);
        init_done = 1;
    }

    // fork: convX on s1, convW on s2, CSR chain stays on the capture stream
    cudaEventRecord(evFork, 0);
    cudaStreamWaitEvent(s1, evFork, 0);
    cudaStreamWaitEvent(s2, evFork, 0);
    convX_kernel<<<(int)(((size_t)NSRC * NF / 4 + 255) / 256), 256, 0, s1>>>(x);
    convW_kernel<<<(NHPAD * 256 + 255) / 256, 256, 0, s2>>>(W1r, W1n, W2n, W2r);

    // main chain: zero -> edgemax -> hist -> scan(3) -> scatter
    zero_kernel<<<(R0 + 255) / 256, 256>>>();
    edgemax_kernel<<<256, 256>>>(eA0, eB0, eA1, eB1);
    hist_kernel<<<(E0C + 255) / 256, 256>>>(eA0, eB0, eA1, eB1);
    scan_local_kernel<<<NTILES, 1024>>>();
    scan_spine_kernel<<<1, 64>>>();
    scan_add_kernel<<<NTILES, 1024>>>();
    scatter_kernel<<<(E0C + 255) / 256, 256>>>(eA0, eB0, eA1, eB1);

    // join convX before gather (reads d_xb)
    cudaEventRecord(evX, s1);
    cudaStreamWaitEvent(0, evX, 0);
    gather_conv_kernel<<<(R0 * 32 + 255) / 256, 256>>>();

    // join convW before mma (reads weight arrays)
    cudaEventRecord(evW, s2);
    cudaStreamWaitEvent(0, evW, 0);
    mma_fused_kernel<<<MTILES, 256, SM_TOT>>>(b1);

    // fused CSR gather-mean + log_softmax
    final_kernel<<<(R1 * 32 + 255) / 256, 256>>>(b2, out);
}